// round 17
// baseline (speedup 1.0000x reference)
#include <cuda_runtime.h>

// Multi-scale 3D LNCC (MermaidNet similarity).
// Scales: (k=12,s=3,OD=57), (k=24,s=6,OD=25), (k=48,s=12,OD=9); dilation=2.
// sim = sum_s w_s * (1 - mean(lncc_s))
//
// oh-tiled pass23 (smem row-span reuse, ~86MB instead of 214MB reads),
// init/final kernels folded away (2 launches total, last-block writes output).
// Shared buffers are function-scope (inside pass23_all only) so pass1_all
// carries zero static smem.

#define IMG 192
#define IMG2 (IMG * IMG)

__device__ float  g_T1a[5 * 57 * IMG2];   // ~42 MB  (k=12)
__device__ float  g_T1b[5 * 25 * IMG2];   // ~18 MB  (k=24)
__device__ float  g_T1c[5 *  9 * IMG2];   // ~6.6 MB (k=48)
__device__ double g_acc;
__device__ unsigned int g_done;

// ---------------------------------------------------------------------------
// Pass 1: segmented sliding-window sum over D.
// ---------------------------------------------------------------------------
template <int K, int S, int OD, int P, int SEGLEN>
__device__ __forceinline__ void pass1_seg(
    const float* __restrict__ I, const float* __restrict__ T,
    float* __restrict__ T1, int h, int p, int seg)
{
    constexpr int SH  = P * S / 2;
    constexpr int chs = OD * IMG2;

    const int w   = threadIdx.x;
    const int col = h * IMG + w;

    const int L  = (OD - p + P - 1) / P;
    const int i0 = seg * SEGLEN;
    if (i0 >= L) return;
    const int iend = (i0 + SEGLEN < L) ? (i0 + SEGLEN) : L;

    int od = p + P * i0;

    float si = 0.f, st = 0.f, si2 = 0.f, st2 = 0.f, sit = 0.f;
    {
        const int d0 = od * S;
#pragma unroll
        for (int i = 0; i < K; ++i) {
            const int idx = (d0 + 2 * i) * IMG2 + col;
            const float vi = I[idx];
            const float vt = T[idx];
            si += vi; st += vt; si2 += vi * vi; st2 += vt * vt; sit += vi * vt;
        }
    }

    for (int i = i0; ; ) {
        const int o = od * IMG2 + col;
        T1[o          ] = si;
        T1[o +     chs] = st;
        T1[o + 2 * chs] = si2;
        T1[o + 3 * chs] = st2;
        T1[o + 4 * chs] = sit;

        if (++i >= iend) break;

        const int base_old = od * S;
#pragma unroll
        for (int t = 0; t < SH; ++t) {
            {
                const int idx = (base_old + 2 * t) * IMG2 + col;
                const float vi = I[idx];
                const float vt = T[idx];
                si -= vi; st -= vt; si2 -= vi * vi; st2 -= vt * vt; sit -= vi * vt;
            }
            {
                const int idx = (base_old + 2 * (K + t)) * IMG2 + col;
                const float vi = I[idx];
                const float vt = T[idx];
                si += vi; st += vt; si2 += vi * vi; st2 += vt * vt; sit += vi * vt;
            }
        }
        od += P;
    }
}

// scale0: 192h*2p*4seg=1536; scale1: 192h*5seg=960; scale2: 192h*3seg=576.
__global__ void pass1_all(const float* __restrict__ I, const float* __restrict__ T) {
    if (blockIdx.x == 0 && threadIdx.x == 0) {
        g_acc  = 1.0;   // sum of weights; lncc means subtracted by pass23
        g_done = 0u;
    }
    int b = blockIdx.x;
    if (b < 1536) {
        const int h = b % IMG;
        const int r = b / IMG;
        pass1_seg<12, 3, 57, 2, 8>(I, T, g_T1a, h, r & 1, r >> 1);
    } else if (b < 1536 + 960) {
        b -= 1536;
        pass1_seg<24, 6, 25, 1, 5>(I, T, g_T1b, b % IMG, 0, b / IMG);
    } else {
        b -= 1536 + 960;
        pass1_seg<48, 12, 9, 1, 3>(I, T, g_T1c, b % IMG, 0, b / IMG);
    }
}

// ---------------------------------------------------------------------------
// Pass 2+3, oh-tiled: block per (od, tile of T oh-rows).
//  - per channel: load the shared h-row span into smem once, compute T
//    H-window sums per thread (kept in registers).
//  - RS=1: all rows (odd S mixes parity); RS=2: even rows only (even S).
//  - then per oh: stage 5-channel H-sum row in smem, compute W-window + LNCC.
// ---------------------------------------------------------------------------
#define ROWBUF_MAX 54

template <int K, int S, int OD, int T, int RS, int ROWCNT>
__device__ __forceinline__ float pass23_tile(
    const float* __restrict__ T1, int od, int ohb,
    float (*rowbuf)[IMG], float (*row5)[IMG])
{
    constexpr int chs = OD * IMG2;
    const int w = threadIdx.x;
    const int hb0 = ohb * S;

    float hs[5][T];

#pragma unroll
    for (int c = 0; c < 5; ++c) {
        const float* __restrict__ src = T1 + c * chs + od * IMG2;
        // load span rows (coalesced over w)
#pragma unroll 4
        for (int rr = 0; rr < ROWCNT; ++rr) {
            const int hh = hb0 + rr * RS;
            rowbuf[rr][w] = (hh < IMG) ? src[hh * IMG + w] : 0.f;
        }
        __syncthreads();
#pragma unroll
        for (int t = 0; t < T; ++t) {
            float acc = 0.f;
#pragma unroll
            for (int j = 0; j < K; ++j) {
                const int idx = (RS == 1) ? (t * S + 2 * j) : (t * (S / 2) + j);
                acc += rowbuf[idx][w];
            }
            hs[c][t] = acc;
        }
        __syncthreads();
    }

    float part = 0.f;
#pragma unroll
    for (int t = 0; t < T; ++t) {
#pragma unroll
        for (int c = 0; c < 5; ++c) row5[c][w] = hs[c][t];
        __syncthreads();
        const int oh = ohb + t;
        if (w < OD && oh < OD) {
            const int wbase = w * S;
            float s[5];
#pragma unroll
            for (int c = 0; c < 5; ++c) {
                float acc = 0.f;
#pragma unroll
                for (int l = 0; l < K; ++l) acc += row5[c][wbase + 2 * l];
                s[c] = acc;
            }
            const float numel = (float)K * (float)K * (float)K;
            const float cross = s[4] - s[0] * s[1] / numel;
            const float ivar  = s[2] - s[0] * s[0] / numel;
            const float tvar  = s[3] - s[1] * s[1] / numel;
            part += cross * cross / (ivar * tvar + 1e-5f);
        }
        __syncthreads();
    }
    return part;
}

// Grid: scale0: 57od*8tiles=456; scale1: 25*4=100; scale2: 9*5=45. Total 601.
#define P23_NBLOCKS 601

__global__ void pass23_all(float* __restrict__ out) {
    __shared__ float s_rowbuf[ROWBUF_MAX][IMG];   // 41.5 KB
    __shared__ float s_row5[5][IMG];              //  3.8 KB
    __shared__ float s_wred[6];

    int b = blockIdx.x;
    double negw;
    float part;
    if (b < 456) {
        part = pass23_tile<12, 3, 57, 8, 1, 44>(g_T1a, b / 8, (b % 8) * 8,
                                                s_rowbuf, s_row5);
        negw = -0.1 / 185193.0;
    } else if (b < 456 + 100) {
        b -= 456;
        part = pass23_tile<24, 6, 25, 8, 2, 45>(g_T1b, b / 4, (b % 4) * 8,
                                                s_rowbuf, s_row5);
        negw = -0.3 / 15625.0;
    } else {
        b -= 456 + 100;
        part = pass23_tile<48, 12, 9, 2, 2, 54>(g_T1c, b / 5, (b % 5) * 2,
                                                s_rowbuf, s_row5);
        negw = -0.6 / 729.0;
    }

    // block reduce (192 threads = 6 warps)
    const int w = threadIdx.x;
#pragma unroll
    for (int o = 16; o > 0; o >>= 1)
        part += __shfl_down_sync(0xffffffffu, part, o);
    if ((w & 31) == 0) s_wred[w >> 5] = part;
    __syncthreads();

    if (w == 0) {
        float tot = s_wred[0] + s_wred[1] + s_wred[2]
                  + s_wred[3] + s_wred[4] + s_wred[5];
        atomicAdd(&g_acc, negw * (double)tot);
        __threadfence();
        const unsigned int old = atomicAdd(&g_done, 1u);
        if (old == P23_NBLOCKS - 1) {
            out[0] = (float)(*(volatile double*)&g_acc);
        }
    }
}

extern "C" void kernel_launch(void* const* d_in, const int* in_sizes, int n_in,
                              void* d_out, int out_size) {
    const float* I0 = (const float*)d_in[0];
    const float* I1 = (const float*)d_in[1];
    float* out = (float*)d_out;

    pass1_all<<<3072, IMG>>>(I0, I1);
    pass23_all<<<P23_NBLOCKS, IMG>>>(out);
}